// round 11
// baseline (speedup 1.0000x reference)
#include <cuda_runtime.h>

// Problem constants (static per reference)
#define BSZ   128
#define NTOT  129
#define NPT   128          // N
#define GS    16
#define CH    384          // channels
#define CH4   96           // CH / 4 (float4 units per row)
#define EPSW  0.05f
#define RMSEPS 1e-6f

__global__ __launch_bounds__(128, 12)
void K_Rectify_38216619000515_kernel(
    const float* __restrict__ f,        // (B, NTOT, CH)
    const float* __restrict__ distance, // (B, N, GS)
    const float* __restrict__ rf,       // (NTOT, CH)
    const float* __restrict__ knorm_w,  // (CH,)
    const int*   __restrict__ idx,      // (B, N, GS), int32, values in [0, B*N)
    float*       __restrict__ out)      // (B, NTOT, CH)
{
    const int tid  = threadIdx.x;
    const int w    = tid >> 5;
    const int lane = tid & 31;
    const int bn   = (blockIdx.x << 2) + w;     // one point per warp, 0..16383
    const int b    = bn >> 7;
    const int n    = bn & 127;

    // lanes 0..15 hold the per-g weight/offset table in registers
    float wt = 0.0f;
    int   off = 0;
    if (lane < GS) {
        const float d = __ldg(distance + bn * GS + lane);
        wt  = 1.0f / (d + EPSW);
        const int r = __ldg(idx + bn * GS + lane) & (BSZ * NPT - 1);
        off = ((r >> 7) * NTOT + (r & 127) + 1) * CH4;     // float4 units
    }

    // wsum: butterfly over lanes 0..15, then broadcast
    float ws = wt;
    ws += __shfl_xor_sync(0xffffffffu, ws, 8);
    ws += __shfl_xor_sync(0xffffffffu, ws, 4);
    ws += __shfl_xor_sync(0xffffffffu, ws, 2);
    ws += __shfl_xor_sync(0xffffffffu, ws, 1);
    const float invw = 1.0f / __shfl_sync(0xffffffffu, ws, 0);

    const float4* f4 = (const float4*)f;

    // cls token passthrough: out[b,0,:] = f[b,0,:]  (3 float4 per lane)
    if (n == 0) {
        const int base = b * (NTOT * CH4);
        ((float4*)out)[base +      lane] = __ldg(f4 + base +      lane);
        ((float4*)out)[base + 32 + lane] = __ldg(f4 + base + 32 + lane);
        ((float4*)out)[base + 64 + lane] = __ldg(f4 + base + 64 + lane);
    }

    // gather: 16 rows x 3 LDG.128, all independent; table broadcast via shuffle pipe
    float4 a0 = make_float4(0.f,0.f,0.f,0.f);
    float4 a1 = make_float4(0.f,0.f,0.f,0.f);
    float4 a2 = make_float4(0.f,0.f,0.f,0.f);
#pragma unroll
    for (int g = 0; g < GS; ++g) {
        const int   o  = __shfl_sync(0xffffffffu, off, g);
        const float wg = __shfl_sync(0xffffffffu, wt,  g);
        const float4 v0 = __ldg(f4 + o +      lane);
        const float4 v1 = __ldg(f4 + o + 32 + lane);
        const float4 v2 = __ldg(f4 + o + 64 + lane);
        a0.x = fmaf(wg, v0.x, a0.x); a0.y = fmaf(wg, v0.y, a0.y);
        a0.z = fmaf(wg, v0.z, a0.z); a0.w = fmaf(wg, v0.w, a0.w);
        a1.x = fmaf(wg, v1.x, a1.x); a1.y = fmaf(wg, v1.y, a1.y);
        a1.z = fmaf(wg, v1.z, a1.z); a1.w = fmaf(wg, v1.w, a1.w);
        a2.x = fmaf(wg, v2.x, a2.x); a2.y = fmaf(wg, v2.y, a2.y);
        a2.z = fmaf(wg, v2.z, a2.z); a2.w = fmaf(wg, v2.w, a2.w);
    }

    const int xrow = (b * NTOT + 1 + n) * CH4;
    const float4 x0 = __ldg(f4 + xrow +      lane);
    const float4 x1 = __ldg(f4 + xrow + 32 + lane);
    const float4 x2 = __ldg(f4 + xrow + 64 + lane);

    // sf = (sum w*row)/W - x   (weights normalized in reference)
    a0.x = a0.x*invw - x0.x; a0.y = a0.y*invw - x0.y;
    a0.z = a0.z*invw - x0.z; a0.w = a0.w*invw - x0.w;
    a1.x = a1.x*invw - x1.x; a1.y = a1.y*invw - x1.y;
    a1.z = a1.z*invw - x1.z; a1.w = a1.w*invw - x1.w;
    a2.x = a2.x*invw - x2.x; a2.y = a2.y*invw - x2.y;
    a2.z = a2.z*invw - x2.z; a2.w = a2.w*invw - x2.w;

    // in-warp RMS reduction (butterfly -> all lanes)
    float local = a0.x*a0.x + a0.y*a0.y + a0.z*a0.z + a0.w*a0.w
                + a1.x*a1.x + a1.y*a1.y + a1.z*a1.z + a1.w*a1.w
                + a2.x*a2.x + a2.y*a2.y + a2.z*a2.z + a2.w*a2.w;
    local += __shfl_xor_sync(0xffffffffu, local, 16);
    local += __shfl_xor_sync(0xffffffffu, local, 8);
    local += __shfl_xor_sync(0xffffffffu, local, 4);
    local += __shfl_xor_sync(0xffffffffu, local, 2);
    local += __shfl_xor_sync(0xffffffffu, local, 1);
    const float rinv = rsqrtf(local * (1.0f / CH) + RMSEPS);

    const float4* rf4 = (const float4*)rf;
    const float4* kw4 = (const float4*)knorm_w;
    const int rrow = (1 + n) * CH4;
    const float4 r0 = __ldg(rf4 + rrow +      lane);
    const float4 r1 = __ldg(rf4 + rrow + 32 + lane);
    const float4 r2 = __ldg(rf4 + rrow + 64 + lane);
    const float4 k0 = __ldg(kw4 +      lane);
    const float4 k1 = __ldg(kw4 + 32 + lane);
    const float4 k2 = __ldg(kw4 + 64 + lane);

    float4 o;
    o.x = r0.x + x0.x + a0.x*rinv*k0.x;  o.y = r0.y + x0.y + a0.y*rinv*k0.y;
    o.z = r0.z + x0.z + a0.z*rinv*k0.z;  o.w = r0.w + x0.w + a0.w*rinv*k0.w;
    ((float4*)out)[xrow +      lane] = o;
    o.x = r1.x + x1.x + a1.x*rinv*k1.x;  o.y = r1.y + x1.y + a1.y*rinv*k1.y;
    o.z = r1.z + x1.z + a1.z*rinv*k1.z;  o.w = r1.w + x1.w + a1.w*rinv*k1.w;
    ((float4*)out)[xrow + 32 + lane] = o;
    o.x = r2.x + x2.x + a2.x*rinv*k2.x;  o.y = r2.y + x2.y + a2.y*rinv*k2.y;
    o.z = r2.z + x2.z + a2.z*rinv*k2.z;  o.w = r2.w + x2.w + a2.w*rinv*k2.w;
    ((float4*)out)[xrow + 64 + lane] = o;
}

extern "C" void kernel_launch(void* const* d_in, const int* in_sizes, int n_in,
                              void* d_out, int out_size)
{
    const float* f        = (const float*)d_in[0];
    const float* distance = (const float*)d_in[1];
    const float* rf       = (const float*)d_in[2];
    const float* knorm_w  = (const float*)d_in[3];
    const int*   idx      = (const int*)d_in[4];
    float*       out      = (float*)d_out;

    K_Rectify_38216619000515_kernel<<<(BSZ * NPT) / 4, 128>>>(
        f, distance, rf, knorm_w, idx, out);
}